// round 8
// baseline (speedup 1.0000x reference)
#include <cuda_runtime.h>
#include <cuda_bf16.h>
#include <cstdint>

// ---------------- problem constants ----------------
#define NB   128
#define CCH  3
#define HH   128
#define WW   128
#define LL   4096
#define D1   1204
#define D2   4816
#define MROWS (NB*CCH)          // 384
#define K2P  1216               // D1 padded
#define SPLITK 4
#define K1CHUNK (LL/SPLITK)     // 1024

// GEMM tile
#define TM 128
#define TN 128
#define TKC 64
#define ROWH 72                 // smem row stride in halves (64 + 8 pad)
#define NSTAGES 3

#define TILE_H   (128*ROWH)     // 9216 halves
#define A_HI_H   0
#define A_LO_H   (TILE_H)
#define B_HI_H   (2*TILE_H)
#define B_LO_H   (3*TILE_H)
#define STAGE_H  (4*TILE_H)     // 36864 halves = 73728 B
#define SMEM_BYTES (NSTAGES*STAGE_H*2)   // 221184 B

// ---------------- device scratch ----------------
__device__ __align__(16) __nv_bfloat16 g_shi[MROWS*LL];
__device__ __align__(16) __nv_bfloat16 g_slo[MROWS*LL];
__device__ __align__(16) __nv_bfloat16 g_w1hi[D1*LL];
__device__ __align__(16) __nv_bfloat16 g_w1lo[D1*LL];
__device__ __align__(16) __nv_bfloat16 g_w2hi[D2*K2P];
__device__ __align__(16) __nv_bfloat16 g_w2lo[D2*K2P];
__device__ __align__(16) __nv_bfloat16 g_h1hi[MROWS*K2P];
__device__ __align__(16) __nv_bfloat16 g_h1lo[MROWS*K2P];
__device__ __align__(16) float g_hp[SPLITK*MROWS*D1];
__device__ __align__(16) float g_h1[MROWS*D1];
__device__ __align__(16) float g_h2[MROWS*D2];
__device__ float g_aff1[6];
__device__ float g_aff2[6];
__device__ float g_part[3*64*2];

// ---------------- PTX helpers ----------------
__device__ __forceinline__ uint32_t smem_to_u32(const void* p) {
    uint32_t a;
    asm("{ .reg .u64 t; cvta.to.shared.u64 t, %1; cvt.u32.u64 %0, t; }" : "=r"(a) : "l"(p));
    return a;
}
__device__ __forceinline__ void cp16(uint32_t saddr, const void* g, int bytes) {
    asm volatile("cp.async.cg.shared.global [%0], [%1], 16, %2;"
                 :: "r"(saddr), "l"(g), "r"(bytes));
}
#define CP_COMMIT() asm volatile("cp.async.commit_group;" ::: "memory")
#define CP_WAIT(N)  asm volatile("cp.async.wait_group %0;" :: "n"(N) : "memory")

__device__ __forceinline__ void ldsm4(uint32_t* r, uint32_t addr) {
    asm volatile("ldmatrix.sync.aligned.m8n8.x4.shared.b16 {%0,%1,%2,%3}, [%4];"
        : "=r"(r[0]), "=r"(r[1]), "=r"(r[2]), "=r"(r[3]) : "r"(addr));
}
__device__ __forceinline__ void mma_bf16(float* c, const uint32_t* a, const uint32_t* b) {
    asm volatile(
        "mma.sync.aligned.m16n8k16.row.col.f32.bf16.bf16.f32 "
        "{%0,%1,%2,%3}, {%4,%5,%6,%7}, {%8,%9}, {%0,%1,%2,%3};"
        : "+f"(c[0]), "+f"(c[1]), "+f"(c[2]), "+f"(c[3])
        : "r"(a[0]), "r"(a[1]), "r"(a[2]), "r"(a[3]), "r"(b[0]), "r"(b[1]));
}

// pack 4 floats -> hi (4 bf16) and lo (4 bf16) as uint2 each
__device__ __forceinline__ void split4(const float* v, uint2& hiu, uint2& lou) {
    __nv_bfloat16 h[4], l[4];
    #pragma unroll
    for (int j = 0; j < 4; j++) {
        h[j] = __float2bfloat16(v[j]);
        l[j] = __float2bfloat16(v[j] - __bfloat162float(h[j]));
    }
    hiu.x = (uint32_t)__bfloat16_as_ushort(h[0]) | ((uint32_t)__bfloat16_as_ushort(h[1]) << 16);
    hiu.y = (uint32_t)__bfloat16_as_ushort(h[2]) | ((uint32_t)__bfloat16_as_ushort(h[3]) << 16);
    lou.x = (uint32_t)__bfloat16_as_ushort(l[0]) | ((uint32_t)__bfloat16_as_ushort(l[1]) << 16);
    lou.y = (uint32_t)__bfloat16_as_ushort(l[2]) | ((uint32_t)__bfloat16_as_ushort(l[3]) << 16);
}

// ---------------- gather + mask + bf16 hi/lo split ----------------
__global__ void gather_kernel(const float* __restrict__ x,
                              const int*   __restrict__ coords,
                              const float* __restrict__ mask)
{
    int idx = blockIdx.x * blockDim.x + threadIdx.x;
    if (idx >= MROWS * LL) return;
    int l = idx & (LL - 1);
    int m = idx >> 12;
    int n = m / 3;
    int off = coords[2*l] * WW + coords[2*l + 1];
    float v = x[(size_t)m * (HH*WW) + off];
    if (mask[(size_t)n * LL + l] < 0.3f) v = 0.0f;
    __nv_bfloat16 hi = __float2bfloat16(v);
    g_shi[idx] = hi;
    g_slo[idx] = __float2bfloat16(v - __bfloat162float(hi));
}

// ---------------- fp32 -> bf16 hi/lo, vectorized x4, K padded to ldOut ----------------
__global__ void convert_split_kernel(const float* __restrict__ in, int K, int ldOut,
                                     __nv_bfloat16* __restrict__ hi,
                                     __nv_bfloat16* __restrict__ lo, long total4)
{
    long i4 = (long)blockIdx.x * blockDim.x + threadIdx.x;
    if (i4 >= total4) return;
    long idx = i4 * 4;
    int r = (int)(idx / ldOut);
    int c = (int)(idx % ldOut);
    float v[4];
    if (c + 3 < K) {
        float4 f = *reinterpret_cast<const float4*>(in + (size_t)r * K + c);
        v[0] = f.x; v[1] = f.y; v[2] = f.z; v[3] = f.w;
    } else {
        #pragma unroll
        for (int j = 0; j < 4; j++)
            v[j] = (c + j < K) ? in[(size_t)r * K + c + j] : 0.0f;
    }
    uint2 hu, lu;
    split4(v, hu, lu);
    *reinterpret_cast<uint2*>(hi + idx) = hu;
    *reinterpret_cast<uint2*>(lo + idx) = lu;
}

// ---------------- h1 -> BN1 affine -> bf16 hi/lo, padded to K2P, x4 ----------------
__global__ void convert_h1_kernel()
{
    int i4 = blockIdx.x * blockDim.x + threadIdx.x;
    if (i4 >= MROWS * K2P / 4) return;
    int idx = i4 * 4;
    int r = idx / K2P;
    int c = idx % K2P;
    int ch = r % 3;
    float a = g_aff1[ch], b = g_aff1[3 + ch];
    float v[4] = {0.0f, 0.0f, 0.0f, 0.0f};
    if (c + 3 < D1) {
        float4 f = *reinterpret_cast<const float4*>(g_h1 + (size_t)r * D1 + c);
        v[0] = f.x * a + b; v[1] = f.y * a + b; v[2] = f.z * a + b; v[3] = f.w * a + b;
    } else {
        #pragma unroll
        for (int j = 0; j < 4; j++)
            if (c + j < D1) v[j] = g_h1[(size_t)r * D1 + c + j] * a + b;
    }
    uint2 hu, lu;
    split4(v, hu, lu);
    *reinterpret_cast<uint2*>(g_h1hi + idx) = hu;
    *reinterpret_cast<uint2*>(g_h1lo + idx) = lu;
}

// ---------------- mma.sync bf16x3 GEMM: C = A * B^T ----------------
// CTA 128x128, 512 threads (16 warps 4x4, warp 32x32), BK=64, 3-stage cp.async,
// register double-buffered fragments (prefetch k16 step s+1 during MMAs of s).
__global__ __launch_bounds__(512)
void gemm_bf16x3(const __nv_bfloat16* __restrict__ Ahi, const __nv_bfloat16* __restrict__ Alo, int lda,
                 const __nv_bfloat16* __restrict__ Bhi, const __nv_bfloat16* __restrict__ Blo,
                 int ldb, int Brows,
                 float* __restrict__ C, int Ncols, int ldc,
                 int kLen, size_t zStride,
                 const float* __restrict__ colBias, int applyLeaky)
{
    extern __shared__ __align__(16) __nv_bfloat16 smem[];
    uint32_t smem_u32 = smem_to_u32(smem);

    int tid  = threadIdx.x;
    int wid  = tid >> 5;
    int lane = tid & 31;
    int m0 = blockIdx.y * TM;
    int n0 = blockIdx.x * TN;
    C += (size_t)blockIdx.z * zStride;
    int k0 = blockIdx.z * kLen;
    int nIter = kLen / TKC;

    int wm = (wid & 3) * 32;
    int wn = (wid >> 2) * 32;

    float acc[2][4][4];
    #pragma unroll
    for (int i = 0; i < 2; i++)
        #pragma unroll
        for (int j = 0; j < 4; j++)
            #pragma unroll
            for (int q = 0; q < 4; q++) acc[i][j][q] = 0.0f;

    // loader: 4 tiles x 1024 16B-chunks, 512 threads -> 2 chunks per tile per thread
    auto load_stage = [&](int stage, int kt) {
        int kbase = k0 + kt * TKC;
        uint32_t sbase = smem_u32 + (uint32_t)stage * STAGE_H * 2;
        #pragma unroll
        for (int it = 0; it < 2; it++) {
            int c = tid + it * 512;
            int row = c >> 3;
            int c16 = c & 7;
            uint32_t so = (uint32_t)(row * ROWH + c16 * 8) * 2;
            size_t ao = (size_t)(m0 + row) * lda + kbase + c16 * 8;
            cp16(sbase + A_HI_H*2 + so, Ahi + ao, 16);
            cp16(sbase + A_LO_H*2 + so, Alo + ao, 16);
            int brow = n0 + row;
            int bytes = (brow < Brows) ? 16 : 0;
            int rcl = (brow < Brows) ? brow : (Brows - 1);
            size_t bo = (size_t)rcl * ldb + kbase + c16 * 8;
            cp16(sbase + B_HI_H*2 + so, Bhi + bo, bytes);
            cp16(sbase + B_LO_H*2 + so, Blo + bo, bytes);
        }
    };

    load_stage(0, 0); CP_COMMIT();
    load_stage(1, 1); CP_COMMIT();

    int rowA = lane & 15;
    int colA = (lane >> 4) * 8;
    int r8  = lane & 7;
    int grp = lane >> 3;
    int rowB = ((grp & 1) << 3) + r8;
    int colB = (grp >> 1) * 8;

    // double-buffered fragments
    uint32_t ah[2][2][4], al[2][2][4], bh[2][4][2], bl[2][4][2];

    auto load_frags = [&](int buf, uint32_t sbase, int kk) {
        #pragma unroll
        for (int mi = 0; mi < 2; mi++) {
            uint32_t off = (uint32_t)((wm + mi*16 + rowA) * ROWH + kk + colA) * 2;
            ldsm4(ah[buf][mi], sbase + A_HI_H*2 + off);
            ldsm4(al[buf][mi], sbase + A_LO_H*2 + off);
        }
        #pragma unroll
        for (int nh = 0; nh < 2; nh++) {
            uint32_t off = (uint32_t)((wn + nh*16 + rowB) * ROWH + kk + colB) * 2;
            uint32_t t[4];
            ldsm4(t, sbase + B_HI_H*2 + off);
            bh[buf][nh*2][0] = t[0]; bh[buf][nh*2][1] = t[2];
            bh[buf][nh*2+1][0] = t[1]; bh[buf][nh*2+1][1] = t[3];
            ldsm4(t, sbase + B_LO_H*2 + off);
            bl[buf][nh*2][0] = t[0]; bl[buf][nh*2][1] = t[2];
            bl[buf][nh*2+1][0] = t[1]; bl[buf][nh*2+1][1] = t[3];
        }
    };

    for (int kt = 0; kt < nIter; kt++) {
        CP_WAIT(1);
        __syncthreads();
        if (kt + 2 < nIter) { load_stage((kt + 2) % NSTAGES, kt + 2); CP_COMMIT(); }

        uint32_t sbase = smem_u32 + (uint32_t)(kt % NSTAGES) * STAGE_H * 2;
        load_frags(0, sbase, 0);
        #pragma unroll
        for (int s = 0; s < TKC/16; s++) {
            int cur = s & 1;
            if (s + 1 < TKC/16) load_frags(cur ^ 1, sbase, (s + 1) * 16);
            // hi*hi first (independent), then corrections (chains of 2)
            #pragma unroll
            for (int mi = 0; mi < 2; mi++)
                #pragma unroll
                for (int ni = 0; ni < 4; ni++)
                    mma_bf16(acc[mi][ni], ah[cur][mi], bh[cur][ni]);
            #pragma unroll
            for (int mi = 0; mi < 2; mi++)
                #pragma unroll
                for (int ni = 0; ni < 4; ni++) {
                    mma_bf16(acc[mi][ni], ah[cur][mi], bl[cur][ni]);
                    mma_bf16(acc[mi][ni], al[cur][mi], bh[cur][ni]);
                }
        }
        __syncthreads();
    }

    // -------- epilogue: float2 stores --------
    #pragma unroll
    for (int mi = 0; mi < 2; mi++) {
        int r0 = m0 + wm + mi*16 + (lane >> 2);
        #pragma unroll
        for (int ni = 0; ni < 4; ni++) {
            int c0 = n0 + wn + ni*8 + (lane & 3)*2;
            if (c0 < Ncols) {
                float2 b2v = colBias ? *reinterpret_cast<const float2*>(colBias + c0)
                                     : make_float2(0.0f, 0.0f);
                float2 v0 = make_float2(acc[mi][ni][0] + b2v.x, acc[mi][ni][1] + b2v.y);
                float2 v1 = make_float2(acc[mi][ni][2] + b2v.x, acc[mi][ni][3] + b2v.y);
                if (applyLeaky) {
                    v0.x = (v0.x >= 0.0f) ? v0.x : 0.01f * v0.x;
                    v0.y = (v0.y >= 0.0f) ? v0.y : 0.01f * v0.y;
                    v1.x = (v1.x >= 0.0f) ? v1.x : 0.01f * v1.x;
                    v1.y = (v1.y >= 0.0f) ? v1.y : 0.01f * v1.y;
                }
                *reinterpret_cast<float2*>(C + (size_t)r0 * ldc + c0) = v0;
                *reinterpret_cast<float2*>(C + (size_t)(r0 + 8) * ldc + c0) = v1;
            }
        }
    }
}

// ---------------- splitK combine + bias + leaky -> h1 (fp32), x4 ----------------
__global__ void combine_kernel(const float* __restrict__ b1)
{
    int i4 = blockIdx.x * blockDim.x + threadIdx.x;
    if (i4 >= MROWS * D1 / 4) return;
    int idx = i4 * 4;
    const int MN = MROWS * D1;
    float4 a0 = *reinterpret_cast<const float4*>(g_hp + idx);
    float4 a1 = *reinterpret_cast<const float4*>(g_hp + MN + idx);
    float4 a2 = *reinterpret_cast<const float4*>(g_hp + 2*MN + idx);
    float4 a3 = *reinterpret_cast<const float4*>(g_hp + 3*MN + idx);
    float4 bb = *reinterpret_cast<const float4*>(b1 + (idx % D1));
    float4 v;
    v.x = a0.x + a1.x + a2.x + a3.x + bb.x;
    v.y = a0.y + a1.y + a2.y + a3.y + bb.y;
    v.z = a0.z + a1.z + a2.z + a3.z + bb.z;
    v.w = a0.w + a1.w + a2.w + a3.w + bb.w;
    v.x = (v.x >= 0.0f) ? v.x : 0.01f * v.x;
    v.y = (v.y >= 0.0f) ? v.y : 0.01f * v.y;
    v.z = (v.z >= 0.0f) ? v.z : 0.01f * v.z;
    v.w = (v.w >= 0.0f) ? v.w : 0.01f * v.w;
    *reinterpret_cast<float4*>(g_h1 + idx) = v;
}

// ---------------- BN stats stage 1: grid (3, 64), 2 rows per block ----------------
__global__ void stats_part_kernel(const float* __restrict__ H, int Ncols)
{
    int c = blockIdx.x, chunk = blockIdx.y;
    float s = 0.0f, sq = 0.0f;
    int nc4 = Ncols >> 2;
    for (int r = chunk * 2; r < chunk * 2 + 2; r++) {
        const float* row = H + (size_t)(r * 3 + c) * Ncols;
        const float4* row4 = reinterpret_cast<const float4*>(row);
        for (int col = threadIdx.x; col < nc4; col += blockDim.x) {
            float4 v = row4[col];
            s  += v.x + v.y + v.z + v.w;
            sq += v.x*v.x + v.y*v.y + v.z*v.z + v.w*v.w;
        }
        for (int col = (nc4 << 2) + threadIdx.x; col < Ncols; col += blockDim.x) {
            float v = row[col];
            s += v; sq += v * v;
        }
    }
    #pragma unroll
    for (int o = 16; o; o >>= 1) {
        s  += __shfl_xor_sync(0xffffffffu, s,  o);
        sq += __shfl_xor_sync(0xffffffffu, sq, o);
    }
    __shared__ float sh0[8], sh1[8];
    int lane = threadIdx.x & 31, wid = threadIdx.x >> 5;
    if (lane == 0) { sh0[wid] = s; sh1[wid] = sq; }
    __syncthreads();
    if (threadIdx.x < 32) {
        int nw = blockDim.x >> 5;
        s  = (lane < nw) ? sh0[lane] : 0.0f;
        sq = (lane < nw) ? sh1[lane] : 0.0f;
        #pragma unroll
        for (int o = 16; o; o >>= 1) {
            s  += __shfl_xor_sync(0xffffffffu, s,  o);
            sq += __shfl_xor_sync(0xffffffffu, sq, o);
        }
        if (lane == 0) {
            g_part[(c * 64 + chunk) * 2 + 0] = s;
            g_part[(c * 64 + chunk) * 2 + 1] = sq;
        }
    }
}

__global__ void stats_fin_kernel(int Ncols,
                                 const float* __restrict__ gamma,
                                 const float* __restrict__ beta,
                                 float* __restrict__ aff)
{
    int c = threadIdx.x;
    if (c >= 3) return;
    float s = 0.0f, sq = 0.0f;
    for (int i = 0; i < 64; i++) {
        s  += g_part[(c * 64 + i) * 2 + 0];
        sq += g_part[(c * 64 + i) * 2 + 1];
    }
    float cnt  = (float)NB * (float)Ncols;
    float mean = s / cnt;
    float var  = sq / cnt - mean * mean;
    float a = gamma[c] * rsqrtf(var + 1e-5f);
    aff[c]     = a;
    aff[3 + c] = beta[c] - mean * a;
}

// ---------------- final elementwise BN2 affine -> output, x4 ----------------
__global__ void final_kernel(float* __restrict__ out)
{
    int i4 = blockIdx.x * blockDim.x + threadIdx.x;
    if (i4 >= MROWS * D2 / 4) return;
    int idx = i4 * 4;
    int c = (idx / D2) % 3;
    float a = g_aff2[c], b = g_aff2[3 + c];
    float4 v = *reinterpret_cast<const float4*>(g_h2 + idx);
    v.x = v.x * a + b; v.y = v.y * a + b; v.z = v.z * a + b; v.w = v.w * a + b;
    *reinterpret_cast<float4*>(out + idx) = v;
}

// ---------------- launch ----------------
extern "C" void kernel_launch(void* const* d_in, const int* in_sizes, int n_in,
                              void* d_out, int out_size)
{
    const float* x      = (const float*)d_in[0];
    const int*   coords = (const int*)  d_in[1];
    const float* mask   = (const float*)d_in[2];
    const float* W1     = (const float*)d_in[3];
    const float* b1     = (const float*)d_in[4];
    const float* g1     = (const float*)d_in[5];
    const float* be1    = (const float*)d_in[6];
    const float* W2     = (const float*)d_in[7];
    const float* b2     = (const float*)d_in[8];
    const float* g2     = (const float*)d_in[9];
    const float* be2    = (const float*)d_in[10];
    float* out = (float*)d_out;

    static bool inited = false;
    static __nv_bfloat16 *p_shi, *p_slo, *p_w1hi, *p_w1lo, *p_w2hi, *p_w2lo, *p_h1hi, *p_h1lo;
    static float *p_hp, *p_h1, *p_h2, *p_a1, *p_a2;
    if (!inited) {
        cudaGetSymbolAddress((void**)&p_shi,  g_shi);
        cudaGetSymbolAddress((void**)&p_slo,  g_slo);
        cudaGetSymbolAddress((void**)&p_w1hi, g_w1hi);
        cudaGetSymbolAddress((void**)&p_w1lo, g_w1lo);
        cudaGetSymbolAddress((void**)&p_w2hi, g_w2hi);
        cudaGetSymbolAddress((void**)&p_w2lo, g_w2lo);
        cudaGetSymbolAddress((void**)&p_h1hi, g_h1hi);
        cudaGetSymbolAddress((void**)&p_h1lo, g_h1lo);
        cudaGetSymbolAddress((void**)&p_hp,   g_hp);
        cudaGetSymbolAddress((void**)&p_h1,   g_h1);
        cudaGetSymbolAddress((void**)&p_h2,   g_h2);
        cudaGetSymbolAddress((void**)&p_a1,   g_aff1);
        cudaGetSymbolAddress((void**)&p_a2,   g_aff2);
        cudaFuncSetAttribute(gemm_bf16x3, cudaFuncAttributeMaxDynamicSharedMemorySize, SMEM_BYTES);
        inited = true;
    }

    // 1) gather + mask + split -> s hi/lo
    gather_kernel<<<(MROWS*LL + 255) / 256, 256>>>(x, coords, mask);

    // 2) W1, W2 -> bf16 hi/lo (vectorized x4)
    {
        long t1 = (long)D1 * LL / 4;
        convert_split_kernel<<<(unsigned)((t1 + 255) / 256), 256>>>(W1, LL, LL, p_w1hi, p_w1lo, t1);
        long t2 = (long)D2 * K2P / 4;
        convert_split_kernel<<<(unsigned)((t2 + 255) / 256), 256>>>(W2, D1, K2P, p_w2hi, p_w2lo, t2);
    }

    // 3) GEMM1 split-K: hp[z] = s * W1^T (K slice)
    {
        dim3 grid((D1 + TN - 1) / TN, MROWS / TM, SPLITK);   // (10, 3, 4)
        gemm_bf16x3<<<grid, 512, SMEM_BYTES>>>(
            p_shi, p_slo, LL,
            p_w1hi, p_w1lo, LL, D1,
            p_hp, D1, D1,
            K1CHUNK, (size_t)MROWS * D1,
            nullptr, 0);
    }

    // 4) combine + b1 + leaky -> h1 (fp32)
    combine_kernel<<<(MROWS*D1/4 + 255) / 256, 256>>>(b1);

    // 5) BN1 stats -> affine1; fold into bf16 conversion of h1
    stats_part_kernel<<<dim3(3, 64), 256>>>(p_h1, D1);
    stats_fin_kernel<<<1, 32>>>(D1, g1, be1, p_a1);
    convert_h1_kernel<<<(MROWS*K2P/4 + 255) / 256, 256>>>();

    // 6) GEMM2: h2 = leaky(h1n * W2^T + b2)
    {
        dim3 grid((D2 + TN - 1) / TN, MROWS / TM, 1);        // (38, 3, 1)
        gemm_bf16x3<<<grid, 512, SMEM_BYTES>>>(
            p_h1hi, p_h1lo, K2P,
            p_w2hi, p_w2lo, K2P, D2,
            p_h2, D2, D2,
            K2P, 0,
            b2, 1);
    }

    // 7) BN2 stats -> affine2
    stats_part_kernel<<<dim3(3, 64), 256>>>(p_h2, D2);
    stats_fin_kernel<<<1, 32>>>(D2, g2, be2, p_a2);

    // 8) final affine -> out
    final_kernel<<<(MROWS*D2/4 + 255) / 256, 256>>>(out);
}

// round 9
// speedup vs baseline: 1.0054x; 1.0054x over previous
#include <cuda_runtime.h>
#include <cuda_bf16.h>
#include <cstdint>

// ---------------- problem constants ----------------
#define NB   128
#define CCH  3
#define HH   128
#define WW   128
#define LL   4096
#define D1   1204
#define D2   4816
#define MROWS (NB*CCH)          // 384
#define K2P  1216
#define SPLITK1 8
#define SPLITK2 2
#define K1CHUNK (LL/SPLITK1)    // 512
#define K2CHUNK (K2P/SPLITK2)   // 608

// GEMM tile
#define TM 128
#define TN 128
#define TKC 32
#define ROWH 32                 // swizzled, no pad
#define NSTAGES 3

#define TILE_H   (128*ROWH)     // 4096 halves = 8192 B
#define A_HI_H   0
#define A_LO_H   (TILE_H)
#define B_HI_H   (2*TILE_H)
#define B_LO_H   (3*TILE_H)
#define STAGE_H  (4*TILE_H)     // 16384 halves = 32768 B
#define SMEM_BYTES (NSTAGES*STAGE_H*2)   // 98304 B -> 2 CTAs/SM

// swizzle: 16B chunk index XOR'd with (row>>1)&3 ; byte offset within tile
__device__ __forceinline__ uint32_t sw_off(int row, int chunk) {
    return (uint32_t)((row * ROWH + ((chunk ^ ((row >> 1) & 3)) << 3)) * 2);
}

// ---------------- device scratch ----------------
__device__ __align__(16) __nv_bfloat16 g_shi[MROWS*LL];
__device__ __align__(16) __nv_bfloat16 g_slo[MROWS*LL];
__device__ __align__(16) __nv_bfloat16 g_w1hi[D1*LL];
__device__ __align__(16) __nv_bfloat16 g_w1lo[D1*LL];
__device__ __align__(16) __nv_bfloat16 g_w2hi[D2*K2P];
__device__ __align__(16) __nv_bfloat16 g_w2lo[D2*K2P];
__device__ __align__(16) __nv_bfloat16 g_h1hi[MROWS*K2P];
__device__ __align__(16) __nv_bfloat16 g_h1lo[MROWS*K2P];
// shared split-K partial buffer: 8*384*1204 == 2*384*4816 == 3,698,688 floats
__device__ __align__(16) float g_hp[SPLITK1*MROWS*D1];
__device__ __align__(16) float g_h1[MROWS*D1];
__device__ __align__(16) float g_h2[MROWS*D2];
__device__ float g_aff1[6];
__device__ float g_aff2[6];
__device__ float g_part[3*64*2];

// ---------------- PTX helpers ----------------
__device__ __forceinline__ uint32_t smem_to_u32(const void* p) {
    uint32_t a;
    asm("{ .reg .u64 t; cvta.to.shared.u64 t, %1; cvt.u32.u64 %0, t; }" : "=r"(a) : "l"(p));
    return a;
}
__device__ __forceinline__ void cp16(uint32_t saddr, const void* g, int bytes) {
    asm volatile("cp.async.cg.shared.global [%0], [%1], 16, %2;"
                 :: "r"(saddr), "l"(g), "r"(bytes));
}
#define CP_COMMIT() asm volatile("cp.async.commit_group;" ::: "memory")
#define CP_WAIT(N)  asm volatile("cp.async.wait_group %0;" :: "n"(N) : "memory")

__device__ __forceinline__ void ldsm4(uint32_t* r, uint32_t addr) {
    asm volatile("ldmatrix.sync.aligned.m8n8.x4.shared.b16 {%0,%1,%2,%3}, [%4];"
        : "=r"(r[0]), "=r"(r[1]), "=r"(r[2]), "=r"(r[3]) : "r"(addr));
}
__device__ __forceinline__ void mma_bf16(float* c, const uint32_t* a, const uint32_t* b) {
    asm volatile(
        "mma.sync.aligned.m16n8k16.row.col.f32.bf16.bf16.f32 "
        "{%0,%1,%2,%3}, {%4,%5,%6,%7}, {%8,%9}, {%0,%1,%2,%3};"
        : "+f"(c[0]), "+f"(c[1]), "+f"(c[2]), "+f"(c[3])
        : "r"(a[0]), "r"(a[1]), "r"(a[2]), "r"(a[3]), "r"(b[0]), "r"(b[1]));
}

__device__ __forceinline__ void split4(const float* v, uint2& hiu, uint2& lou) {
    __nv_bfloat16 h[4], l[4];
    #pragma unroll
    for (int j = 0; j < 4; j++) {
        h[j] = __float2bfloat16(v[j]);
        l[j] = __float2bfloat16(v[j] - __bfloat162float(h[j]));
    }
    hiu.x = (uint32_t)__bfloat16_as_ushort(h[0]) | ((uint32_t)__bfloat16_as_ushort(h[1]) << 16);
    hiu.y = (uint32_t)__bfloat16_as_ushort(h[2]) | ((uint32_t)__bfloat16_as_ushort(h[3]) << 16);
    lou.x = (uint32_t)__bfloat16_as_ushort(l[0]) | ((uint32_t)__bfloat16_as_ushort(l[1]) << 16);
    lou.y = (uint32_t)__bfloat16_as_ushort(l[2]) | ((uint32_t)__bfloat16_as_ushort(l[3]) << 16);
}

// ---------------- gather + mask + bf16 hi/lo split ----------------
__global__ void gather_kernel(const float* __restrict__ x,
                              const int*   __restrict__ coords,
                              const float* __restrict__ mask)
{
    int idx = blockIdx.x * blockDim.x + threadIdx.x;
    if (idx >= MROWS * LL) return;
    int l = idx & (LL - 1);
    int m = idx >> 12;
    int n = m / 3;
    int off = coords[2*l] * WW + coords[2*l + 1];
    float v = x[(size_t)m * (HH*WW) + off];
    if (mask[(size_t)n * LL + l] < 0.3f) v = 0.0f;
    __nv_bfloat16 hi = __float2bfloat16(v);
    g_shi[idx] = hi;
    g_slo[idx] = __float2bfloat16(v - __bfloat162float(hi));
}

// ---------------- fp32 -> bf16 hi/lo, x4, K padded to ldOut ----------------
__global__ void convert_split_kernel(const float* __restrict__ in, int K, int ldOut,
                                     __nv_bfloat16* __restrict__ hi,
                                     __nv_bfloat16* __restrict__ lo, long total4)
{
    long i4 = (long)blockIdx.x * blockDim.x + threadIdx.x;
    if (i4 >= total4) return;
    long idx = i4 * 4;
    int r = (int)(idx / ldOut);
    int c = (int)(idx % ldOut);
    float v[4];
    if (c + 3 < K) {
        float4 f = *reinterpret_cast<const float4*>(in + (size_t)r * K + c);
        v[0] = f.x; v[1] = f.y; v[2] = f.z; v[3] = f.w;
    } else {
        #pragma unroll
        for (int j = 0; j < 4; j++)
            v[j] = (c + j < K) ? in[(size_t)r * K + c + j] : 0.0f;
    }
    uint2 hu, lu;
    split4(v, hu, lu);
    *reinterpret_cast<uint2*>(hi + idx) = hu;
    *reinterpret_cast<uint2*>(lo + idx) = lu;
}

// ---------------- h1 -> BN1 affine -> bf16 hi/lo, padded to K2P, x4 ----------------
__global__ void convert_h1_kernel()
{
    int i4 = blockIdx.x * blockDim.x + threadIdx.x;
    if (i4 >= MROWS * K2P / 4) return;
    int idx = i4 * 4;
    int r = idx / K2P;
    int c = idx % K2P;
    int ch = r % 3;
    float a = g_aff1[ch], b = g_aff1[3 + ch];
    float v[4] = {0.0f, 0.0f, 0.0f, 0.0f};
    if (c + 3 < D1) {
        float4 f = *reinterpret_cast<const float4*>(g_h1 + (size_t)r * D1 + c);
        v[0] = f.x * a + b; v[1] = f.y * a + b; v[2] = f.z * a + b; v[3] = f.w * a + b;
    } else {
        #pragma unroll
        for (int j = 0; j < 4; j++)
            if (c + j < D1) v[j] = g_h1[(size_t)r * D1 + c + j] * a + b;
    }
    uint2 hu, lu;
    split4(v, hu, lu);
    *reinterpret_cast<uint2*>(g_h1hi + idx) = hu;
    *reinterpret_cast<uint2*>(g_h1lo + idx) = lu;
}

// ---------------- mma.sync bf16x3 GEMM: C_partial = A * B^T (split-K) ----------------
// CTA 128x128, 256 threads (8 warps 2x4, warp 64x32), BK=32, 3-stage, swizzled smem,
// 2 CTAs/SM. Epilogue writes raw partial sums (bias/leaky applied in combine).
__global__ __launch_bounds__(256, 2)
void gemm_bf16x3(const __nv_bfloat16* __restrict__ Ahi, const __nv_bfloat16* __restrict__ Alo, int lda,
                 const __nv_bfloat16* __restrict__ Bhi, const __nv_bfloat16* __restrict__ Blo,
                 int ldb, int Brows,
                 float* __restrict__ C, int Ncols, int ldc,
                 int kLen, size_t zStride)
{
    extern __shared__ __align__(16) __nv_bfloat16 smem[];
    uint32_t smem_u32 = smem_to_u32(smem);

    int tid  = threadIdx.x;
    int wid  = tid >> 5;
    int lane = tid & 31;
    int m0 = blockIdx.y * TM;
    int n0 = blockIdx.x * TN;
    C += (size_t)blockIdx.z * zStride;
    int k0 = blockIdx.z * kLen;
    int nIter = kLen / TKC;

    int wm = (wid & 1) * 64;   // 2 warps in M
    int wn = (wid >> 1) * 32;  // 4 warps in N

    float acc[4][4][4];
    #pragma unroll
    for (int i = 0; i < 4; i++)
        #pragma unroll
        for (int j = 0; j < 4; j++)
            #pragma unroll
            for (int q = 0; q < 4; q++) acc[i][j][q] = 0.0f;

    // loader: 4 tiles x 512 chunks, 256 threads -> 2 chunks per tile per thread
    auto load_stage = [&](int stage, int kt) {
        int kbase = k0 + kt * TKC;
        uint32_t sbase = smem_u32 + (uint32_t)stage * STAGE_H * 2;
        #pragma unroll
        for (int it = 0; it < 2; it++) {
            int c = tid + it * 256;        // 0..511
            int row = c >> 2;              // 0..127
            int c16 = c & 3;
            uint32_t so = sw_off(row, c16);
            size_t ao = (size_t)(m0 + row) * lda + kbase + c16 * 8;
            cp16(sbase + A_HI_H*2 + so, Ahi + ao, 16);
            cp16(sbase + A_LO_H*2 + so, Alo + ao, 16);
            int brow = n0 + row;
            int bytes = (brow < Brows) ? 16 : 0;
            int rcl = (brow < Brows) ? brow : (Brows - 1);
            size_t bo = (size_t)rcl * ldb + kbase + c16 * 8;
            cp16(sbase + B_HI_H*2 + so, Bhi + bo, bytes);
            cp16(sbase + B_LO_H*2 + so, Blo + bo, bytes);
        }
    };

    load_stage(0, 0); CP_COMMIT();
    load_stage(1, 1); CP_COMMIT();

    int rowA = lane & 15;              // row within 16-row frag
    int chA  = lane >> 4;              // 0/1: +0 or +8 halves (chunk within k16)
    int r8  = lane & 7;
    int grp = lane >> 3;
    int rowB = ((grp & 1) << 3) + r8;
    int chB  = grp >> 1;

    for (int kt = 0; kt < nIter; kt++) {
        CP_WAIT(1);
        __syncthreads();
        if (kt + 2 < nIter) { load_stage((kt + 2) % NSTAGES, kt + 2); CP_COMMIT(); }

        uint32_t sbase = smem_u32 + (uint32_t)(kt % NSTAGES) * STAGE_H * 2;
        #pragma unroll
        for (int s = 0; s < TKC/16; s++) {
            int kchunk = s * 2;        // chunk base of this k16 step
            uint32_t ah[4][4], al[4][4], bh[4][2], bl[4][2];
            #pragma unroll
            for (int mi = 0; mi < 4; mi++) {
                int row = wm + mi*16 + rowA;
                uint32_t off = sw_off(row, kchunk + chA);
                ldsm4(ah[mi], sbase + A_HI_H*2 + off);
                ldsm4(al[mi], sbase + A_LO_H*2 + off);
            }
            #pragma unroll
            for (int nh = 0; nh < 2; nh++) {
                int row = wn + nh*16 + rowB;
                uint32_t off = sw_off(row, kchunk + chB);
                uint32_t t[4];
                ldsm4(t, sbase + B_HI_H*2 + off);
                bh[nh*2][0] = t[0]; bh[nh*2][1] = t[2];
                bh[nh*2+1][0] = t[1]; bh[nh*2+1][1] = t[3];
                ldsm4(t, sbase + B_LO_H*2 + off);
                bl[nh*2][0] = t[0]; bl[nh*2][1] = t[2];
                bl[nh*2+1][0] = t[1]; bl[nh*2+1][1] = t[3];
            }
            #pragma unroll
            for (int mi = 0; mi < 4; mi++)
                #pragma unroll
                for (int ni = 0; ni < 4; ni++)
                    mma_bf16(acc[mi][ni], ah[mi], bh[ni]);
            #pragma unroll
            for (int mi = 0; mi < 4; mi++)
                #pragma unroll
                for (int ni = 0; ni < 4; ni++) {
                    mma_bf16(acc[mi][ni], ah[mi], bl[ni]);
                    mma_bf16(acc[mi][ni], al[mi], bh[ni]);
                }
        }
        __syncthreads();
    }

    // -------- epilogue: raw partials, float2 stores --------
    #pragma unroll
    for (int mi = 0; mi < 4; mi++) {
        int r0 = m0 + wm + mi*16 + (lane >> 2);
        #pragma unroll
        for (int ni = 0; ni < 4; ni++) {
            int c0 = n0 + wn + ni*8 + (lane & 3)*2;
            if (c0 < Ncols) {
                *reinterpret_cast<float2*>(C + (size_t)r0 * ldc + c0)
                    = make_float2(acc[mi][ni][0], acc[mi][ni][1]);
                *reinterpret_cast<float2*>(C + (size_t)(r0 + 8) * ldc + c0)
                    = make_float2(acc[mi][ni][2], acc[mi][ni][3]);
            }
        }
    }
}

// ---------------- split-K combine + bias + leaky, x4, generic ----------------
__global__ void combine_kernel(const float* __restrict__ bias,
                               float* __restrict__ outp, int Ncols, int nparts)
{
    int i4 = blockIdx.x * blockDim.x + threadIdx.x;
    int total4 = MROWS * Ncols / 4;
    if (i4 >= total4) return;
    int idx = i4 * 4;
    const int MN = MROWS * Ncols;
    float4 v = *reinterpret_cast<const float4*>(g_hp + idx);
    for (int p = 1; p < nparts; p++) {
        float4 a = *reinterpret_cast<const float4*>(g_hp + (size_t)p * MN + idx);
        v.x += a.x; v.y += a.y; v.z += a.z; v.w += a.w;
    }
    float4 bb = *reinterpret_cast<const float4*>(bias + (idx % Ncols));
    v.x += bb.x; v.y += bb.y; v.z += bb.z; v.w += bb.w;
    v.x = (v.x >= 0.0f) ? v.x : 0.01f * v.x;
    v.y = (v.y >= 0.0f) ? v.y : 0.01f * v.y;
    v.z = (v.z >= 0.0f) ? v.z : 0.01f * v.z;
    v.w = (v.w >= 0.0f) ? v.w : 0.01f * v.w;
    *reinterpret_cast<float4*>(outp + idx) = v;
}

// ---------------- BN stats stage 1 ----------------
__global__ void stats_part_kernel(const float* __restrict__ H, int Ncols)
{
    int c = blockIdx.x, chunk = blockIdx.y;
    float s = 0.0f, sq = 0.0f;
    int nc4 = Ncols >> 2;
    for (int r = chunk * 2; r < chunk * 2 + 2; r++) {
        const float* row = H + (size_t)(r * 3 + c) * Ncols;
        const float4* row4 = reinterpret_cast<const float4*>(row);
        for (int col = threadIdx.x; col < nc4; col += blockDim.x) {
            float4 v = row4[col];
            s  += v.x + v.y + v.z + v.w;
            sq += v.x*v.x + v.y*v.y + v.z*v.z + v.w*v.w;
        }
        for (int col = (nc4 << 2) + threadIdx.x; col < Ncols; col += blockDim.x) {
            float v = row[col];
            s += v; sq += v * v;
        }
    }
    #pragma unroll
    for (int o = 16; o; o >>= 1) {
        s  += __shfl_xor_sync(0xffffffffu, s,  o);
        sq += __shfl_xor_sync(0xffffffffu, sq, o);
    }
    __shared__ float sh0[8], sh1[8];
    int lane = threadIdx.x & 31, wid = threadIdx.x >> 5;
    if (lane == 0) { sh0[wid] = s; sh1[wid] = sq; }
    __syncthreads();
    if (threadIdx.x < 32) {
        int nw = blockDim.x >> 5;
        s  = (lane < nw) ? sh0[lane] : 0.0f;
        sq = (lane < nw) ? sh1[lane] : 0.0f;
        #pragma unroll
        for (int o = 16; o; o >>= 1) {
            s  += __shfl_xor_sync(0xffffffffu, s,  o);
            sq += __shfl_xor_sync(0xffffffffu, sq, o);
        }
        if (lane == 0) {
            g_part[(c * 64 + chunk) * 2 + 0] = s;
            g_part[(c * 64 + chunk) * 2 + 1] = sq;
        }
    }
}

__global__ void stats_fin_kernel(int Ncols,
                                 const float* __restrict__ gamma,
                                 const float* __restrict__ beta,
                                 float* __restrict__ aff)
{
    int c = threadIdx.x;
    if (c >= 3) return;
    float s = 0.0f, sq = 0.0f;
    for (int i = 0; i < 64; i++) {
        s  += g_part[(c * 64 + i) * 2 + 0];
        sq += g_part[(c * 64 + i) * 2 + 1];
    }
    float cnt  = (float)NB * (float)Ncols;
    float mean = s / cnt;
    float var  = sq / cnt - mean * mean;
    float a = gamma[c] * rsqrtf(var + 1e-5f);
    aff[c]     = a;
    aff[3 + c] = beta[c] - mean * a;
}

// ---------------- final BN2 affine -> output, x4 ----------------
__global__ void final_kernel(float* __restrict__ out)
{
    int i4 = blockIdx.x * blockDim.x + threadIdx.x;
    if (i4 >= MROWS * D2 / 4) return;
    int idx = i4 * 4;
    int c = (idx / D2) % 3;
    float a = g_aff2[c], b = g_aff2[3 + c];
    float4 v = *reinterpret_cast<const float4*>(g_h2 + idx);
    v.x = v.x * a + b; v.y = v.y * a + b; v.z = v.z * a + b; v.w = v.w * a + b;
    *reinterpret_cast<float4*>(out + idx) = v;
}

// ---------------- launch ----------------
extern "C" void kernel_launch(void* const* d_in, const int* in_sizes, int n_in,
                              void* d_out, int out_size)
{
    const float* x      = (const float*)d_in[0];
    const int*   coords = (const int*)  d_in[1];
    const float* mask   = (const float*)d_in[2];
    const float* W1     = (const float*)d_in[3];
    const float* b1     = (const float*)d_in[4];
    const float* g1     = (const float*)d_in[5];
    const float* be1    = (const float*)d_in[6];
    const float* W2     = (const float*)d_in[7];
    const float* b2     = (const float*)d_in[8];
    const float* g2     = (const float*)d_in[9];
    const float* be2    = (const float*)d_in[10];
    float* out = (float*)d_out;

    static bool inited = false;
    static __nv_bfloat16 *p_shi, *p_slo, *p_w1hi, *p_w1lo, *p_w2hi, *p_w2lo, *p_h1hi, *p_h1lo;
    static float *p_hp, *p_h1, *p_h2, *p_a1, *p_a2;
    if (!inited) {
        cudaGetSymbolAddress((void**)&p_shi,  g_shi);
        cudaGetSymbolAddress((void**)&p_slo,  g_slo);
        cudaGetSymbolAddress((void**)&p_w1hi, g_w1hi);
        cudaGetSymbolAddress((void**)&p_w1lo, g_w1lo);
        cudaGetSymbolAddress((void**)&p_w2hi, g_w2hi);
        cudaGetSymbolAddress((void**)&p_w2lo, g_w2lo);
        cudaGetSymbolAddress((void**)&p_h1hi, g_h1hi);
        cudaGetSymbolAddress((void**)&p_h1lo, g_h1lo);
        cudaGetSymbolAddress((void**)&p_hp,   g_hp);
        cudaGetSymbolAddress((void**)&p_h1,   g_h1);
        cudaGetSymbolAddress((void**)&p_h2,   g_h2);
        cudaGetSymbolAddress((void**)&p_a1,   g_aff1);
        cudaGetSymbolAddress((void**)&p_a2,   g_aff2);
        cudaFuncSetAttribute(gemm_bf16x3, cudaFuncAttributeMaxDynamicSharedMemorySize, SMEM_BYTES);
        inited = true;
    }

    // 1) gather + mask + split -> s hi/lo
    gather_kernel<<<(MROWS*LL + 255) / 256, 256>>>(x, coords, mask);

    // 2) W1, W2 -> bf16 hi/lo
    {
        long t1 = (long)D1 * LL / 4;
        convert_split_kernel<<<(unsigned)((t1 + 255) / 256), 256>>>(W1, LL, LL, p_w1hi, p_w1lo, t1);
        long t2 = (long)D2 * K2P / 4;
        convert_split_kernel<<<(unsigned)((t2 + 255) / 256), 256>>>(W2, D1, K2P, p_w2hi, p_w2lo, t2);
    }

    // 3) GEMM1 split-K=8 -> partials
    {
        dim3 grid((D1 + TN - 1) / TN, MROWS / TM, SPLITK1);  // (10, 3, 8) = 240 CTAs
        gemm_bf16x3<<<grid, 256, SMEM_BYTES>>>(
            p_shi, p_slo, LL,
            p_w1hi, p_w1lo, LL, D1,
            p_hp, D1, D1,
            K1CHUNK, (size_t)MROWS * D1);
    }

    // 4) combine(8) + b1 + leaky -> h1
    combine_kernel<<<(MROWS*D1/4 + 255) / 256, 256>>>(b1, p_h1, D1, SPLITK1);

    // 5) BN1 stats -> affine1 -> h1 bf16 conversion
    stats_part_kernel<<<dim3(3, 64), 256>>>(p_h1, D1);
    stats_fin_kernel<<<1, 32>>>(D1, g1, be1, p_a1);
    convert_h1_kernel<<<(MROWS*K2P/4 + 255) / 256, 256>>>();

    // 6) GEMM2 split-K=2 -> partials
    {
        dim3 grid((D2 + TN - 1) / TN, MROWS / TM, SPLITK2);  // (38, 3, 2) = 228 CTAs
        gemm_bf16x3<<<grid, 256, SMEM_BYTES>>>(
            p_h1hi, p_h1lo, K2P,
            p_w2hi, p_w2lo, K2P, D2,
            p_hp, D2, D2,
            K2CHUNK, (size_t)MROWS * D2);
    }

    // 7) combine(2) + b2 + leaky -> h2
    combine_kernel<<<(MROWS*D2/4 + 255) / 256, 256>>>(b2, p_h2, D2, SPLITK2);

    // 8) BN2 stats -> affine2
    stats_part_kernel<<<dim3(3, 64), 256>>>(p_h2, D2);
    stats_fin_kernel<<<1, 32>>>(D2, g2, be2, p_a2);

    // 9) final affine -> out
    final_kernel<<<(MROWS*D2/4 + 255) / 256, 256>>>(out);
}